// round 1
// baseline (speedup 1.0000x reference)
#include <cuda_runtime.h>
#include <cuda_bf16.h>
#include <math_constants.h>

// Problem constants (fixed by the dataset shapes)
constexpr int B    = 32;
constexpr int N    = 2000;
constexpr int NPAD = 2048;
constexpr int D    = 25088;      // 512*7*7
constexpr int KC   = 16;         // K-chunks for dots kernel
constexpr int DC   = D / KC;     // 1568
constexpr int TK   = 32;         // k-tile depth
constexpr int TN   = 128;        // n-tile width (dots kernel)
constexpr int TIT  = DC / TK;    // 49 k-iterations per chunk
constexpr int TDN  = 32;         // n per tile in read kernel
constexpr int NT3  = (N + TDN - 1) / TDN;  // 63

constexpr float EPS   = 1e-8f;
constexpr float PI_2C = 3.14159f * 0.5f;

// Scratch (zero-initialized at module load; w[2000:2048) is never written -> stays 0)
__device__ float g_part[KC * B * NPAD];   // partial dots [kc][b][n]
__device__ float g_msq [KC * NPAD];       // partial sum(m^2) [kc][n]
__device__ float g_w   [B * NPAD];        // softmax weights [b][n]

// Packed fp32x2 FMA (doubles fp32 throughput on sm_103a; ptxas never emits it from C++)
#define FMA2(d, a, b) asm("fma.rn.f32x2 %0, %1, %2, %0;" : "+l"(d) : "l"(a), "l"(b))

// ---------------------------------------------------------------------------
// Kernel 1: partial dots[b,n] over one D-chunk + partial m-norms.
// Grid: (16 n-blocks, 16 k-chunks), 128 threads. Tile 32(b) x 128(n).
// Micro-tile per thread: 4b x 8n, accumulated as 16 f32x2 pairs (paired on n).
// K operand stored DUPLICATED in smem so f32x2 needs no packing ops.
// ---------------------------------------------------------------------------
__global__ __launch_bounds__(128) void dots_kernel(
    const float* __restrict__ key, const float* __restrict__ mem)
{
    const int nb  = blockIdx.x;          // 0..15
    const int kc  = blockIdx.y;          // 0..15
    const int tid = threadIdx.x;
    const int bt  = tid & 7;             // micro b-tile   -> b0 = 4*bt
    const int nt  = tid >> 3;            // micro n-tile   -> n0 = 8*nt
    const int n0blk = nb * TN;
    const int d0c   = kc * DC;

    __shared__ __align__(16) float Ks[TK][68];   // [kk][2b] duplicated (+4 pad)
    __shared__ __align__(16) float Ms[TK][132];  // [kk][n]  transposed  (+4 pad)

    unsigned long long acc[4][4];
    #pragma unroll
    for (int i = 0; i < 4; i++)
        #pragma unroll
        for (int j = 0; j < 4; j++) acc[i][j] = 0ull;

    float msqa[8];
    #pragma unroll
    for (int p = 0; p < 8; p++) msqa[p] = 0.f;

    const int lcol = tid & 7;            // float4 column 0..7
    const int lrow = tid >> 3;           // 0..15

    for (int it = 0; it < TIT; ++it) {
        const int d0 = d0c + it * TK;

        float4 rk[2], rm[8];
        #pragma unroll
        for (int p = 0; p < 2; p++) {
            const int b = lrow + 16 * p;
            rk[p] = *(const float4*)&key[b * D + d0 + 4 * lcol];
        }
        #pragma unroll
        for (int p = 0; p < 8; p++) {
            const int n = n0blk + lrow + 16 * p;
            if (n < N) rm[p] = *(const float4*)&mem[(long long)n * D + d0 + 4 * lcol];
            else       rm[p] = make_float4(0.f, 0.f, 0.f, 0.f);
        }

        __syncthreads();
        #pragma unroll
        for (int p = 0; p < 2; p++) {
            const int b = lrow + 16 * p;
            const float v[4] = {rk[p].x, rk[p].y, rk[p].z, rk[p].w};
            #pragma unroll
            for (int i = 0; i < 4; i++) {
                Ks[4 * lcol + i][2 * b]     = v[i];
                Ks[4 * lcol + i][2 * b + 1] = v[i];
            }
        }
        #pragma unroll
        for (int p = 0; p < 8; p++) {
            const int nl = lrow + 16 * p;
            const float v[4] = {rm[p].x, rm[p].y, rm[p].z, rm[p].w};
            msqa[p] = fmaf(v[0], v[0], fmaf(v[1], v[1],
                      fmaf(v[2], v[2], fmaf(v[3], v[3], msqa[p]))));
            #pragma unroll
            for (int i = 0; i < 4; i++) Ms[4 * lcol + i][nl] = v[i];
        }
        __syncthreads();

        #pragma unroll
        for (int kk = 0; kk < TK; ++kk) {
            const ulonglong2 kv0 = *(const ulonglong2*)&Ks[kk][8 * bt];
            const ulonglong2 kv1 = *(const ulonglong2*)&Ks[kk][8 * bt + 4];
            const ulonglong2 mv0 = *(const ulonglong2*)&Ms[kk][8 * nt];
            const ulonglong2 mv1 = *(const ulonglong2*)&Ms[kk][8 * nt + 4];
            const unsigned long long ka[4] = {kv0.x, kv0.y, kv1.x, kv1.y};
            const unsigned long long ma[4] = {mv0.x, mv0.y, mv1.x, mv1.y};
            #pragma unroll
            for (int i = 0; i < 4; i++)
                #pragma unroll
                for (int j = 0; j < 4; j++)
                    FMA2(acc[i][j], ka[i], ma[j]);
        }
    }

    // Write dot partials: thread covers b = 4*bt+bi, n = n0blk + 8*nt + 2*j + {0,1}
    #pragma unroll
    for (int bi = 0; bi < 4; bi++) {
        const int b = 4 * bt + bi;
        const float2 u0 = *(const float2*)&acc[bi][0];
        const float2 u1 = *(const float2*)&acc[bi][1];
        const float2 u2 = *(const float2*)&acc[bi][2];
        const float2 u3 = *(const float2*)&acc[bi][3];
        float* dst = &g_part[(kc * B + b) * NPAD + n0blk + 8 * nt];
        *(float4*)(dst + 0) = make_float4(u0.x, u0.y, u1.x, u1.y);
        *(float4*)(dst + 4) = make_float4(u2.x, u2.y, u3.x, u3.y);
    }

    // Reduce m-norm partials across the 8 threads sharing each n row
    __shared__ float Msqs[TN];
    Msqs[tid] = 0.f;
    __syncthreads();
    #pragma unroll
    for (int p = 0; p < 8; p++) atomicAdd(&Msqs[lrow + 16 * p], msqa[p]);
    __syncthreads();
    g_msq[kc * NPAD + n0blk + tid] = Msqs[tid];
}

// ---------------------------------------------------------------------------
// Kernel 2: per-b key norm + reduce partials + cos -> tan -> softmax -> w
// Grid: 32 blocks (one per b), 256 threads.
// ---------------------------------------------------------------------------
__global__ __launch_bounds__(256) void softmax_kernel(const float* __restrict__ key)
{
    const int b   = blockIdx.x;
    const int tid = threadIdx.x;
    __shared__ float red[256];

    // ||k_b||
    float s = 0.f;
    for (int i = tid; i < D; i += 256) {
        const float v = key[b * D + i];
        s = fmaf(v, v, s);
    }
    red[tid] = s; __syncthreads();
    for (int o = 128; o > 0; o >>= 1) {
        if (tid < o) red[tid] += red[tid + o];
        __syncthreads();
    }
    const float knorm = fmaxf(sqrtf(red[0]), EPS);
    __syncthreads();

    float sv[8];
    float lmax = -CUDART_INF_F;
    #pragma unroll
    for (int j = 0; j < 8; j++) {
        const int n = tid + 256 * j;
        if (n < N) {
            float dot = 0.f, ms = 0.f;
            #pragma unroll
            for (int c = 0; c < KC; c++) {
                dot += g_part[(c * B + b) * NPAD + n];
                ms  += g_msq[c * NPAD + n];
            }
            const float mn = fmaxf(sqrtf(ms), EPS);
            sv[j] = tanf((dot / (knorm * mn)) * PI_2C);
            lmax = fmaxf(lmax, sv[j]);
        } else {
            sv[j] = -CUDART_INF_F;
        }
    }
    red[tid] = lmax; __syncthreads();
    for (int o = 128; o > 0; o >>= 1) {
        if (tid < o) red[tid] = fmaxf(red[tid], red[tid + o]);
        __syncthreads();
    }
    const float mx = red[0];
    __syncthreads();

    float ev[8];
    float ls = 0.f;
    #pragma unroll
    for (int j = 0; j < 8; j++) {
        const int n = tid + 256 * j;
        ev[j] = (n < N) ? expf(sv[j] - mx) : 0.f;
        ls += ev[j];
    }
    red[tid] = ls; __syncthreads();
    for (int o = 128; o > 0; o >>= 1) {
        if (tid < o) red[tid] += red[tid + o];
        __syncthreads();
    }
    const float inv = 1.f / red[0];
    #pragma unroll
    for (int j = 0; j < 8; j++) {
        const int n = tid + 256 * j;
        if (n < N) g_w[b * NPAD + n] = ev[j] * inv;
    }
}

// ---------------------------------------------------------------------------
// Kernel 3: out[b,d] = sum_n w[b,n] * m[n,d].
// Grid: 196 d-blocks (25088/128), 128 threads. Tile 32(b) x 128(d), loop n.
// Same f32x2 structure: w duplicated in smem, m tile natural layout.
// ---------------------------------------------------------------------------
__global__ __launch_bounds__(128) void read_kernel(
    const float* __restrict__ mem, float* __restrict__ out)
{
    const int db  = blockIdx.x;          // 0..195
    const int tid = threadIdx.x;
    const int bt  = tid & 7;             // b0 = 4*bt
    const int dt  = tid >> 3;            // d0 = 8*dt
    const int d0blk = db * 128;

    __shared__ __align__(16) float Ws [TDN][68];   // [n][2b] duplicated (+4 pad)
    __shared__ __align__(16) float Ms2[TDN][128];  // [n][d] natural

    unsigned long long acc[4][4];
    #pragma unroll
    for (int i = 0; i < 4; i++)
        #pragma unroll
        for (int j = 0; j < 4; j++) acc[i][j] = 0ull;

    const int wcol = tid & 7;            // w float4 col
    const int wrow = tid >> 3;           // 0..15
    const int mcol = tid & 31;           // m float4 col
    const int mrow = tid >> 5;           // 0..3

    for (int itn = 0; itn < NT3; ++itn) {
        const int n0 = itn * TDN;

        float4 rw[2], rm[8];
        #pragma unroll
        for (int p = 0; p < 2; p++) {
            const int bb = wrow + 16 * p;
            // g_w[2000:2048) is identically 0 (never written), so no guard needed
            rw[p] = *(const float4*)&g_w[bb * NPAD + n0 + 4 * wcol];
        }
        #pragma unroll
        for (int p = 0; p < 8; p++) {
            const int nl = mrow + 4 * p;
            const int n  = n0 + nl;
            if (n < N) rm[p] = *(const float4*)&mem[(long long)n * D + d0blk + 4 * mcol];
            else       rm[p] = make_float4(0.f, 0.f, 0.f, 0.f);
        }

        __syncthreads();
        #pragma unroll
        for (int p = 0; p < 2; p++) {
            const int bb = wrow + 16 * p;
            const float v[4] = {rw[p].x, rw[p].y, rw[p].z, rw[p].w};
            #pragma unroll
            for (int i = 0; i < 4; i++) {
                Ws[4 * wcol + i][2 * bb]     = v[i];
                Ws[4 * wcol + i][2 * bb + 1] = v[i];
            }
        }
        #pragma unroll
        for (int p = 0; p < 8; p++) {
            const int nl = mrow + 4 * p;
            *(float4*)&Ms2[nl][4 * mcol] = rm[p];
        }
        __syncthreads();

        #pragma unroll
        for (int kk = 0; kk < TDN; ++kk) {
            const ulonglong2 wv0 = *(const ulonglong2*)&Ws[kk][8 * bt];
            const ulonglong2 wv1 = *(const ulonglong2*)&Ws[kk][8 * bt + 4];
            const ulonglong2 mv0 = *(const ulonglong2*)&Ms2[kk][8 * dt];
            const ulonglong2 mv1 = *(const ulonglong2*)&Ms2[kk][8 * dt + 4];
            const unsigned long long wa[4] = {wv0.x, wv0.y, wv1.x, wv1.y};
            const unsigned long long ma[4] = {mv0.x, mv0.y, mv1.x, mv1.y};
            #pragma unroll
            for (int i = 0; i < 4; i++)
                #pragma unroll
                for (int j = 0; j < 4; j++)
                    FMA2(acc[i][j], wa[i], ma[j]);
        }
    }

    #pragma unroll
    for (int bi = 0; bi < 4; bi++) {
        const int b = 4 * bt + bi;
        const float2 u0 = *(const float2*)&acc[bi][0];
        const float2 u1 = *(const float2*)&acc[bi][1];
        const float2 u2 = *(const float2*)&acc[bi][2];
        const float2 u3 = *(const float2*)&acc[bi][3];
        float* dst = &out[b * D + d0blk + 8 * dt];
        *(float4*)(dst + 0) = make_float4(u0.x, u0.y, u1.x, u1.y);
        *(float4*)(dst + 4) = make_float4(u2.x, u2.y, u3.x, u3.y);
    }
}

// ---------------------------------------------------------------------------
extern "C" void kernel_launch(void* const* d_in, const int* in_sizes, int n_in,
                              void* d_out, int out_size)
{
    const float* key = (const float*)d_in[0];   // [32, 512, 7, 7]
    const float* mem = (const float*)d_in[1];   // [2000, 512, 7, 7]
    float* out = (float*)d_out;                 // [32, 512, 7, 7]

    dim3 g1(16, KC);
    dots_kernel<<<g1, 128>>>(key, mem);
    softmax_kernel<<<32, 256>>>(key);
    read_kernel<<<D / 128, 128>>>(mem, out);
}

// round 2
// speedup vs baseline: 1.5295x; 1.5295x over previous
#include <cuda_runtime.h>
#include <cuda_bf16.h>
#include <math_constants.h>

// Problem constants (fixed by the dataset shapes)
constexpr int B    = 32;
constexpr int N    = 2000;
constexpr int NPAD = 2048;
constexpr int D    = 25088;        // 512*7*7
constexpr int TK   = 16;           // k-tile depth (dots kernel)
constexpr int ITOT = D / TK;       // 1568 total k-iterations
constexpr int KC   = 37;           // k-chunks -> 8*37 = 296 blocks = 2/SM
constexpr int TDN  = 32;           // n per tile in read kernel
constexpr int NIT3 = 63;           // n-iterations total (covers 2016, zero-padded)
constexpr int NC   = 3;            // n-chunks for read kernel (63 = 3*21)

constexpr float EPS   = 1e-8f;
constexpr float PI_2C = 3.14159f * 0.5f;

// Scratch (zero-initialized at module load; g_w[2000:2048) never written -> stays 0)
__device__ float g_part [KC * B * NPAD];   // partial dots [kc][b][n]
__device__ float g_msq  [KC * NPAD];       // partial sum(m^2) [kc][n]
__device__ float g_w    [B * NPAD];        // softmax weights [b][n]
__device__ float g_rpart[NC * B * D];      // read-kernel partials [nc][b][d]

// Packed fp32x2 FMA (doubles fp32 throughput; ptxas never emits it from C++)
#define FMA2(d, a, b) asm("fma.rn.f32x2 %0, %1, %2, %0;" : "+l"(d) : "l"(a), "l"(b))

// ---------------------------------------------------------------------------
// Kernel 1: partial dots[b,n] over one k-chunk + partial m-norms.
// Grid: (8 n-blocks, 37 k-chunks) = 296 blocks, 256 threads, 2 blocks/SM.
// Tile 32(b) x 256(n); micro-tile 4b x 8n per thread as 16 f32x2 accumulators.
// K operand duplicated in smem so f32x2 needs no packing ops.
// ---------------------------------------------------------------------------
__global__ __launch_bounds__(256, 2) void dots_kernel(
    const float* __restrict__ key, const float* __restrict__ mem)
{
    const int nb  = blockIdx.x;              // 0..7
    const int kc  = blockIdx.y;              // 0..36
    const int tid = threadIdx.x;
    const int bt  = tid & 7;                 // micro b-tile -> b0 = 4*bt
    const int nt  = tid >> 3;                // micro n-tile -> n0 = 8*nt (0..31)
    const int n0blk = nb * 256;

    const int it0 = (kc    ) * ITOT / KC;
    const int it1 = (kc + 1) * ITOT / KC;

    __shared__ __align__(16) float Ks[TK][68];    // [kk][2b] duplicated (+4 pad)
    __shared__ __align__(16) float Ms[TK][260];   // [kk][n]  transposed  (+4 pad)
    __shared__ float Msqs[256];

    unsigned long long acc[4][4];
    #pragma unroll
    for (int i = 0; i < 4; i++)
        #pragma unroll
        for (int j = 0; j < 4; j++) acc[i][j] = 0ull;

    float msqa[4];
    #pragma unroll
    for (int p = 0; p < 4; p++) msqa[p] = 0.f;

    const int lcol = tid & 3;                // float4 column within 16-float row
    const int lrow = tid >> 2;               // 0..63

    for (int it = it0; it < it1; ++it) {
        const int d0 = it * TK;

        float4 rk = make_float4(0.f, 0.f, 0.f, 0.f);
        if (tid < 128) rk = *(const float4*)&key[lrow * D + d0 + 4 * lcol];

        float4 rm[4];
        #pragma unroll
        for (int p = 0; p < 4; p++) {
            const int n = n0blk + lrow + 64 * p;
            if (n < N) rm[p] = *(const float4*)&mem[(long long)n * D + d0 + 4 * lcol];
            else       rm[p] = make_float4(0.f, 0.f, 0.f, 0.f);
        }

        __syncthreads();
        if (tid < 128) {
            const float v[4] = {rk.x, rk.y, rk.z, rk.w};
            #pragma unroll
            for (int i = 0; i < 4; i++) {
                Ks[4 * lcol + i][2 * lrow]     = v[i];
                Ks[4 * lcol + i][2 * lrow + 1] = v[i];
            }
        }
        #pragma unroll
        for (int p = 0; p < 4; p++) {
            const int nl = lrow + 64 * p;
            const float v[4] = {rm[p].x, rm[p].y, rm[p].z, rm[p].w};
            msqa[p] = fmaf(v[0], v[0], fmaf(v[1], v[1],
                      fmaf(v[2], v[2], fmaf(v[3], v[3], msqa[p]))));
            #pragma unroll
            for (int i = 0; i < 4; i++) Ms[4 * lcol + i][nl] = v[i];
        }
        __syncthreads();

        #pragma unroll
        for (int kk = 0; kk < TK; ++kk) {
            const ulonglong2 kv0 = *(const ulonglong2*)&Ks[kk][8 * bt];
            const ulonglong2 kv1 = *(const ulonglong2*)&Ks[kk][8 * bt + 4];
            const ulonglong2 mv0 = *(const ulonglong2*)&Ms[kk][8 * nt];
            const ulonglong2 mv1 = *(const ulonglong2*)&Ms[kk][8 * nt + 4];
            const unsigned long long ka[4] = {kv0.x, kv0.y, kv1.x, kv1.y};
            const unsigned long long ma[4] = {mv0.x, mv0.y, mv1.x, mv1.y};
            #pragma unroll
            for (int i = 0; i < 4; i++)
                #pragma unroll
                for (int j = 0; j < 4; j++)
                    FMA2(acc[i][j], ka[i], ma[j]);
        }
    }

    // Write dot partials: thread covers b = 4*bt+bi, n = n0blk + 8*nt + {0..7}
    #pragma unroll
    for (int bi = 0; bi < 4; bi++) {
        const int b = 4 * bt + bi;
        const float2 u0 = *(const float2*)&acc[bi][0];
        const float2 u1 = *(const float2*)&acc[bi][1];
        const float2 u2 = *(const float2*)&acc[bi][2];
        const float2 u3 = *(const float2*)&acc[bi][3];
        float* dst = &g_part[(kc * B + b) * NPAD + n0blk + 8 * nt];
        *(float4*)(dst + 0) = make_float4(u0.x, u0.y, u1.x, u1.y);
        *(float4*)(dst + 4) = make_float4(u2.x, u2.y, u3.x, u3.y);
    }

    // Reduce m-norm partials: 4 threads (lcol) share each n row
    Msqs[tid] = 0.f;
    __syncthreads();
    #pragma unroll
    for (int p = 0; p < 4; p++) atomicAdd(&Msqs[lrow + 64 * p], msqa[p]);
    __syncthreads();
    g_msq[kc * NPAD + n0blk + tid] = Msqs[tid];
}

// ---------------------------------------------------------------------------
// Kernel 2: per-b key norm + reduce partials + cos -> tan -> softmax -> w
// Grid: 32 blocks (one per b), 256 threads.
// ---------------------------------------------------------------------------
__global__ __launch_bounds__(256) void softmax_kernel(const float* __restrict__ key)
{
    const int b   = blockIdx.x;
    const int tid = threadIdx.x;
    __shared__ float red[256];

    // ||k_b||
    float s = 0.f;
    for (int i = tid; i < D; i += 256) {
        const float v = key[b * D + i];
        s = fmaf(v, v, s);
    }
    red[tid] = s; __syncthreads();
    for (int o = 128; o > 0; o >>= 1) {
        if (tid < o) red[tid] += red[tid + o];
        __syncthreads();
    }
    const float knorm = fmaxf(sqrtf(red[0]), EPS);
    __syncthreads();

    float sv[8];
    float lmax = -CUDART_INF_F;
    #pragma unroll
    for (int j = 0; j < 8; j++) {
        const int n = tid + 256 * j;
        if (n < N) {
            float dot = 0.f, ms = 0.f;
            for (int c = 0; c < KC; c++) {
                dot += g_part[(c * B + b) * NPAD + n];
                ms  += g_msq[c * NPAD + n];
            }
            const float mn = fmaxf(sqrtf(ms), EPS);
            sv[j] = tanf((dot / (knorm * mn)) * PI_2C);
            lmax = fmaxf(lmax, sv[j]);
        } else {
            sv[j] = -CUDART_INF_F;
        }
    }
    red[tid] = lmax; __syncthreads();
    for (int o = 128; o > 0; o >>= 1) {
        if (tid < o) red[tid] = fmaxf(red[tid], red[tid + o]);
        __syncthreads();
    }
    const float mx = red[0];
    __syncthreads();

    float ev[8];
    float ls = 0.f;
    #pragma unroll
    for (int j = 0; j < 8; j++) {
        const int n = tid + 256 * j;
        ev[j] = (n < N) ? expf(sv[j] - mx) : 0.f;
        ls += ev[j];
    }
    red[tid] = ls; __syncthreads();
    for (int o = 128; o > 0; o >>= 1) {
        if (tid < o) red[tid] += red[tid + o];
        __syncthreads();
    }
    const float inv = 1.f / red[0];
    #pragma unroll
    for (int j = 0; j < 8; j++) {
        const int n = tid + 256 * j;
        if (n < N) g_w[b * NPAD + n] = ev[j] * inv;
    }
}

// ---------------------------------------------------------------------------
// Kernel 3: partial out[b,d] = sum over an n-chunk of w[b,n]*m[n,d].
// Grid: (98 d-blocks, 3 n-chunks) = 294 blocks, 256 threads, 2 blocks/SM.
// Tile 32(b) x 256(d); micro 4b x 8d; w duplicated in smem.
// ---------------------------------------------------------------------------
__global__ __launch_bounds__(256, 2) void read_kernel(
    const float* __restrict__ mem)
{
    const int db  = blockIdx.x;              // 0..97
    const int nc  = blockIdx.y;              // 0..2
    const int tid = threadIdx.x;
    const int bt  = tid & 7;                 // b0 = 4*bt
    const int dt  = tid >> 3;                // d0 = 8*dt (0..31)
    const int d0blk = db * 256;

    const int itn0 = nc * (NIT3 / NC);       // 21 iterations per chunk
    const int itn1 = itn0 + (NIT3 / NC);

    __shared__ __align__(16) float Ws [TDN][68];    // [n][2b] duplicated (+4 pad)
    __shared__ __align__(16) float Ms2[TDN][260];   // [n][d] natural (+4 pad)

    unsigned long long acc[4][4];
    #pragma unroll
    for (int i = 0; i < 4; i++)
        #pragma unroll
        for (int j = 0; j < 4; j++) acc[i][j] = 0ull;

    const int wb   = tid >> 3;               // b row for w loads (0..31)
    const int wn   = tid & 7;                // n sub-index
    const int mcol = tid & 63;               // float4 col (0..63)
    const int mrow = tid >> 6;               // 0..3

    for (int itn = itn0; itn < itn1; ++itn) {
        const int n0 = itn * TDN;

        float rw[4];
        #pragma unroll
        for (int p = 0; p < 4; p++)
            rw[p] = g_w[wb * NPAD + n0 + wn + 8 * p];   // zero-padded past N

        float4 rm[8];
        #pragma unroll
        for (int p = 0; p < 8; p++) {
            const int n = n0 + mrow + 4 * p;
            if (n < N) rm[p] = *(const float4*)&mem[(long long)n * D + d0blk + 4 * mcol];
            else       rm[p] = make_float4(0.f, 0.f, 0.f, 0.f);
        }

        __syncthreads();
        #pragma unroll
        for (int p = 0; p < 4; p++) {
            Ws[wn + 8 * p][2 * wb]     = rw[p];
            Ws[wn + 8 * p][2 * wb + 1] = rw[p];
        }
        #pragma unroll
        for (int p = 0; p < 8; p++)
            *(float4*)&Ms2[mrow + 4 * p][4 * mcol] = rm[p];
        __syncthreads();

        #pragma unroll
        for (int kk = 0; kk < TDN; ++kk) {
            const ulonglong2 wv0 = *(const ulonglong2*)&Ws[kk][8 * bt];
            const ulonglong2 wv1 = *(const ulonglong2*)&Ws[kk][8 * bt + 4];
            const ulonglong2 mv0 = *(const ulonglong2*)&Ms2[kk][8 * dt];
            const ulonglong2 mv1 = *(const ulonglong2*)&Ms2[kk][8 * dt + 4];
            const unsigned long long wa[4] = {wv0.x, wv0.y, wv1.x, wv1.y};
            const unsigned long long ma[4] = {mv0.x, mv0.y, mv1.x, mv1.y};
            #pragma unroll
            for (int i = 0; i < 4; i++)
                #pragma unroll
                for (int j = 0; j < 4; j++)
                    FMA2(acc[i][j], wa[i], ma[j]);
        }
    }

    #pragma unroll
    for (int bi = 0; bi < 4; bi++) {
        const int b = 4 * bt + bi;
        const float2 u0 = *(const float2*)&acc[bi][0];
        const float2 u1 = *(const float2*)&acc[bi][1];
        const float2 u2 = *(const float2*)&acc[bi][2];
        const float2 u3 = *(const float2*)&acc[bi][3];
        float* dst = &g_rpart[(nc * B + b) * D + d0blk + 8 * dt];
        *(float4*)(dst + 0) = make_float4(u0.x, u0.y, u1.x, u1.y);
        *(float4*)(dst + 4) = make_float4(u2.x, u2.y, u3.x, u3.y);
    }
}

// ---------------------------------------------------------------------------
// Kernel 4: out = sum of the 3 n-chunk partials (float4 wide).
// ---------------------------------------------------------------------------
__global__ __launch_bounds__(256) void reduce_kernel(float* __restrict__ out)
{
    const int i = blockIdx.x * 256 + threadIdx.x;   // float4 index
    const float4 a = ((const float4*)g_rpart)[i];
    const float4 b = ((const float4*)g_rpart)[i +     B * D / 4];
    const float4 c = ((const float4*)g_rpart)[i + 2 * B * D / 4];
    float4 r;
    r.x = a.x + b.x + c.x;
    r.y = a.y + b.y + c.y;
    r.z = a.z + b.z + c.z;
    r.w = a.w + b.w + c.w;
    ((float4*)out)[i] = r;
}

// ---------------------------------------------------------------------------
extern "C" void kernel_launch(void* const* d_in, const int* in_sizes, int n_in,
                              void* d_out, int out_size)
{
    const float* key = (const float*)d_in[0];   // [32, 512, 7, 7]
    const float* mem = (const float*)d_in[1];   // [2000, 512, 7, 7]
    float* out = (float*)d_out;                 // [32, 512, 7, 7]

    dim3 g1(8, KC);
    dots_kernel<<<g1, 256>>>(key, mem);
    softmax_kernel<<<32, 256>>>(key);
    dim3 g3(D / 256, NC);
    read_kernel<<<g3, 256>>>(mem);
    reduce_kernel<<<B * D / 4 / 256, 256>>>(out);
}

// round 3
// speedup vs baseline: 1.5349x; 1.0035x over previous
#include <cuda_runtime.h>
#include <cuda_bf16.h>
#include <math_constants.h>

// Problem constants (fixed by the dataset shapes)
constexpr int B    = 32;
constexpr int N    = 2000;
constexpr int NPAD = 2048;
constexpr int D    = 25088;        // 512*7*7
constexpr int TK   = 16;           // k-tile depth (dots kernel)
constexpr int ITOT = D / TK;       // 1568 total k-iterations
constexpr int KC   = 37;           // k-chunks -> 8*37 = 296 blocks = 2/SM
constexpr int TDN  = 32;           // n per tile in read kernel
constexpr int NIT3 = 63;           // n-iterations total (covers 2016, zero-padded)
constexpr int NC   = 3;            // n-chunks for read kernel (63 = 3*21)

constexpr float EPS   = 1e-8f;
constexpr float PI_2C = 3.14159f * 0.5f;

// Scratch (zero-initialized at module load; g_w[2000:2048) never written -> stays 0)
__device__ float g_part [KC * B * NPAD];   // partial dots [kc][b][n]
__device__ float g_msq  [KC * NPAD];       // partial sum(m^2) [kc][n]
__device__ float g_w    [B * NPAD];        // softmax weights [b][n]
__device__ float g_rpart[NC * B * D];      // read-kernel partials [nc][b][d]

// Packed fp32x2 FMA (doubles fp32 throughput; ptxas never emits it from C++)
#define FMA2(d, a, b) asm("fma.rn.f32x2 %0, %1, %2, %0;" : "+l"(d) : "l"(a), "l"(b))

// ---------------------------------------------------------------------------
// Kernel 1: partial dots[b,n] over one k-chunk + partial m-norms.
// Grid: (8 n-blocks, 37 k-chunks) = 296 blocks, 256 threads, 2 blocks/SM.
// Tile 32(b) x 256(n); micro-tile 4b x 8n per thread as 16 f32x2 accumulators.
// K operand duplicated in smem so f32x2 needs no packing ops.
// ---------------------------------------------------------------------------
__global__ __launch_bounds__(256, 2) void dots_kernel(
    const float* __restrict__ key, const float* __restrict__ mem)
{
    const int nb  = blockIdx.x;              // 0..7
    const int kc  = blockIdx.y;              // 0..36
    const int tid = threadIdx.x;
    const int bt  = tid & 7;                 // micro b-tile -> b0 = 4*bt
    const int nt  = tid >> 3;                // micro n-tile -> n0 = 8*nt (0..31)
    const int n0blk = nb * 256;

    const int it0 = (kc    ) * ITOT / KC;
    const int it1 = (kc + 1) * ITOT / KC;

    __shared__ __align__(16) float Ks[TK][68];    // [kk][2b] duplicated (+4 pad)
    __shared__ __align__(16) float Ms[TK][260];   // [kk][n]  transposed  (+4 pad)
    __shared__ float Msqs[256];

    unsigned long long acc[4][4];
    #pragma unroll
    for (int i = 0; i < 4; i++)
        #pragma unroll
        for (int j = 0; j < 4; j++) acc[i][j] = 0ull;

    float msqa[4];
    #pragma unroll
    for (int p = 0; p < 4; p++) msqa[p] = 0.f;

    const int lcol = tid & 3;                // float4 column within 16-float row
    const int lrow = tid >> 2;               // 0..63

    for (int it = it0; it < it1; ++it) {
        const int d0 = it * TK;

        float4 rk = make_float4(0.f, 0.f, 0.f, 0.f);
        if (tid < 128) rk = *(const float4*)&key[lrow * D + d0 + 4 * lcol];

        float4 rm[4];
        #pragma unroll
        for (int p = 0; p < 4; p++) {
            const int n = n0blk + lrow + 64 * p;
            if (n < N) rm[p] = *(const float4*)&mem[(long long)n * D + d0 + 4 * lcol];
            else       rm[p] = make_float4(0.f, 0.f, 0.f, 0.f);
        }

        __syncthreads();
        if (tid < 128) {
            const float v[4] = {rk.x, rk.y, rk.z, rk.w};
            #pragma unroll
            for (int i = 0; i < 4; i++) {
                Ks[4 * lcol + i][2 * lrow]     = v[i];
                Ks[4 * lcol + i][2 * lrow + 1] = v[i];
            }
        }
        #pragma unroll
        for (int p = 0; p < 4; p++) {
            const int nl = lrow + 64 * p;
            const float v[4] = {rm[p].x, rm[p].y, rm[p].z, rm[p].w};
            msqa[p] = fmaf(v[0], v[0], fmaf(v[1], v[1],
                      fmaf(v[2], v[2], fmaf(v[3], v[3], msqa[p]))));
            #pragma unroll
            for (int i = 0; i < 4; i++) Ms[4 * lcol + i][nl] = v[i];
        }
        __syncthreads();

        #pragma unroll
        for (int kk = 0; kk < TK; ++kk) {
            const ulonglong2 kv0 = *(const ulonglong2*)&Ks[kk][8 * bt];
            const ulonglong2 kv1 = *(const ulonglong2*)&Ks[kk][8 * bt + 4];
            const ulonglong2 mv0 = *(const ulonglong2*)&Ms[kk][8 * nt];
            const ulonglong2 mv1 = *(const ulonglong2*)&Ms[kk][8 * nt + 4];
            const unsigned long long ka[4] = {kv0.x, kv0.y, kv1.x, kv1.y};
            const unsigned long long ma[4] = {mv0.x, mv0.y, mv1.x, mv1.y};
            #pragma unroll
            for (int i = 0; i < 4; i++)
                #pragma unroll
                for (int j = 0; j < 4; j++)
                    FMA2(acc[i][j], ka[i], ma[j]);
        }
    }

    // Write dot partials: thread covers b = 4*bt+bi, n = n0blk + 8*nt + {0..7}
    #pragma unroll
    for (int bi = 0; bi < 4; bi++) {
        const int b = 4 * bt + bi;
        const float2 u0 = *(const float2*)&acc[bi][0];
        const float2 u1 = *(const float2*)&acc[bi][1];
        const float2 u2 = *(const float2*)&acc[bi][2];
        const float2 u3 = *(const float2*)&acc[bi][3];
        float* dst = &g_part[(kc * B + b) * NPAD + n0blk + 8 * nt];
        *(float4*)(dst + 0) = make_float4(u0.x, u0.y, u1.x, u1.y);
        *(float4*)(dst + 4) = make_float4(u2.x, u2.y, u3.x, u3.y);
    }

    // Reduce m-norm partials: 4 threads (lcol) share each n row
    Msqs[tid] = 0.f;
    __syncthreads();
    #pragma unroll
    for (int p = 0; p < 4; p++) atomicAdd(&Msqs[lrow + 64 * p], msqa[p]);
    __syncthreads();
    g_msq[kc * NPAD + n0blk + tid] = Msqs[tid];
}

// ---------------------------------------------------------------------------
// Kernel 2: per-b key norm + reduce partials + cos -> tan -> softmax -> w
// Grid: 32 blocks (one per b), 256 threads.
// ---------------------------------------------------------------------------
__global__ __launch_bounds__(256) void softmax_kernel(const float* __restrict__ key)
{
    const int b   = blockIdx.x;
    const int tid = threadIdx.x;
    __shared__ float red[256];

    // ||k_b||
    float s = 0.f;
    for (int i = tid; i < D; i += 256) {
        const float v = key[b * D + i];
        s = fmaf(v, v, s);
    }
    red[tid] = s; __syncthreads();
    for (int o = 128; o > 0; o >>= 1) {
        if (tid < o) red[tid] += red[tid + o];
        __syncthreads();
    }
    const float knorm = fmaxf(sqrtf(red[0]), EPS);
    __syncthreads();

    float sv[8];
    float lmax = -CUDART_INF_F;
    #pragma unroll
    for (int j = 0; j < 8; j++) {
        const int n = tid + 256 * j;
        if (n < N) {
            float dot = 0.f, ms = 0.f;
            for (int c = 0; c < KC; c++) {
                dot += g_part[(c * B + b) * NPAD + n];
                ms  += g_msq[c * NPAD + n];
            }
            const float mn = fmaxf(sqrtf(ms), EPS);
            sv[j] = tanf((dot / (knorm * mn)) * PI_2C);
            lmax = fmaxf(lmax, sv[j]);
        } else {
            sv[j] = -CUDART_INF_F;
        }
    }
    red[tid] = lmax; __syncthreads();
    for (int o = 128; o > 0; o >>= 1) {
        if (tid < o) red[tid] = fmaxf(red[tid], red[tid + o]);
        __syncthreads();
    }
    const float mx = red[0];
    __syncthreads();

    float ev[8];
    float ls = 0.f;
    #pragma unroll
    for (int j = 0; j < 8; j++) {
        const int n = tid + 256 * j;
        ev[j] = (n < N) ? expf(sv[j] - mx) : 0.f;
        ls += ev[j];
    }
    red[tid] = ls; __syncthreads();
    for (int o = 128; o > 0; o >>= 1) {
        if (tid < o) red[tid] += red[tid + o];
        __syncthreads();
    }
    const float inv = 1.f / red[0];
    #pragma unroll
    for (int j = 0; j < 8; j++) {
        const int n = tid + 256 * j;
        if (n < N) g_w[b * NPAD + n] = ev[j] * inv;
    }
}

// ---------------------------------------------------------------------------
// Kernel 3: partial out[b,d] = sum over an n-chunk of w[b,n]*m[n,d].
// Grid: (98 d-blocks, 3 n-chunks) = 294 blocks, 256 threads, 2 blocks/SM.
// Tile 32(b) x 256(d); micro 4b x 8d; w duplicated in smem.
// ---------------------------------------------------------------------------
__global__ __launch_bounds__(256, 2) void read_kernel(
    const float* __restrict__ mem)
{
    const int db  = blockIdx.x;              // 0..97
    const int nc  = blockIdx.y;              // 0..2
    const int tid = threadIdx.x;
    const int bt  = tid & 7;                 // b0 = 4*bt
    const int dt  = tid >> 3;                // d0 = 8*dt (0..31)
    const int d0blk = db * 256;

    const int itn0 = nc * (NIT3 / NC);       // 21 iterations per chunk
    const int itn1 = itn0 + (NIT3 / NC);

    __shared__ __align__(16) float Ws [TDN][68];    // [n][2b] duplicated (+4 pad)
    __shared__ __align__(16) float Ms2[TDN][260];   // [n][d] natural (+4 pad)

    unsigned long long acc[4][4];
    #pragma unroll
    for (int i = 0; i < 4; i++)
        #pragma unroll
        for (int j = 0; j < 4; j++) acc[i][j] = 0ull;

    const int wb   = tid >> 3;               // b row for w loads (0..31)
    const int wn   = tid & 7;                // n sub-index
    const int mcol = tid & 63;               // float4 col (0..63)
    const int mrow = tid >> 6;               // 0..3

    for (int itn = itn0; itn < itn1; ++itn) {
        const int n0 = itn * TDN;

        float rw[4];
        #pragma unroll
        for (int p = 0; p < 4; p++)
            rw[p] = g_w[wb * NPAD + n0 + wn + 8 * p];   // zero-padded past N

        float4 rm[8];
        #pragma unroll
        for (int p = 0; p < 8; p++) {
            const int n = n0 + mrow + 4 * p;
            if (n < N) rm[p] = *(const float4*)&mem[(long long)n * D + d0blk + 4 * mcol];
            else       rm[p] = make_float4(0.f, 0.f, 0.f, 0.f);
        }

        __syncthreads();
        #pragma unroll
        for (int p = 0; p < 4; p++) {
            Ws[wn + 8 * p][2 * wb]     = rw[p];
            Ws[wn + 8 * p][2 * wb + 1] = rw[p];
        }
        #pragma unroll
        for (int p = 0; p < 8; p++)
            *(float4*)&Ms2[mrow + 4 * p][4 * mcol] = rm[p];
        __syncthreads();

        #pragma unroll
        for (int kk = 0; kk < TDN; ++kk) {
            const ulonglong2 wv0 = *(const ulonglong2*)&Ws[kk][8 * bt];
            const ulonglong2 wv1 = *(const ulonglong2*)&Ws[kk][8 * bt + 4];
            const ulonglong2 mv0 = *(const ulonglong2*)&Ms2[kk][8 * dt];
            const ulonglong2 mv1 = *(const ulonglong2*)&Ms2[kk][8 * dt + 4];
            const unsigned long long wa[4] = {wv0.x, wv0.y, wv1.x, wv1.y};
            const unsigned long long ma[4] = {mv0.x, mv0.y, mv1.x, mv1.y};
            #pragma unroll
            for (int i = 0; i < 4; i++)
                #pragma unroll
                for (int j = 0; j < 4; j++)
                    FMA2(acc[i][j], wa[i], ma[j]);
        }
    }

    #pragma unroll
    for (int bi = 0; bi < 4; bi++) {
        const int b = 4 * bt + bi;
        const float2 u0 = *(const float2*)&acc[bi][0];
        const float2 u1 = *(const float2*)&acc[bi][1];
        const float2 u2 = *(const float2*)&acc[bi][2];
        const float2 u3 = *(const float2*)&acc[bi][3];
        float* dst = &g_rpart[(nc * B + b) * D + d0blk + 8 * dt];
        *(float4*)(dst + 0) = make_float4(u0.x, u0.y, u1.x, u1.y);
        *(float4*)(dst + 4) = make_float4(u2.x, u2.y, u3.x, u3.y);
    }
}

// ---------------------------------------------------------------------------
// Kernel 4: out = sum of the 3 n-chunk partials (float4 wide).
// ---------------------------------------------------------------------------
__global__ __launch_bounds__(256) void reduce_kernel(float* __restrict__ out)
{
    const int i = blockIdx.x * 256 + threadIdx.x;   // float4 index
    const float4 a = ((const float4*)g_rpart)[i];
    const float4 b = ((const float4*)g_rpart)[i +     B * D / 4];
    const float4 c = ((const float4*)g_rpart)[i + 2 * B * D / 4];
    float4 r;
    r.x = a.x + b.x + c.x;
    r.y = a.y + b.y + c.y;
    r.z = a.z + b.z + c.z;
    r.w = a.w + b.w + c.w;
    ((float4*)out)[i] = r;
}

// ---------------------------------------------------------------------------
extern "C" void kernel_launch(void* const* d_in, const int* in_sizes, int n_in,
                              void* d_out, int out_size)
{
    const float* key = (const float*)d_in[0];   // [32, 512, 7, 7]
    const float* mem = (const float*)d_in[1];   // [2000, 512, 7, 7]
    float* out = (float*)d_out;                 // [32, 512, 7, 7]

    dim3 g1(8, KC);
    dots_kernel<<<g1, 256>>>(key, mem);
    softmax_kernel<<<32, 256>>>(key);
    dim3 g3(D / 256, NC);
    read_kernel<<<g3, 256>>>(mem);
    reduce_kernel<<<B * D / 4 / 256, 256>>>(out);
}

// round 5
// speedup vs baseline: 2.0286x; 1.3217x over previous
#include <cuda_runtime.h>
#include <cuda_bf16.h>
#include <math_constants.h>
#include <cstdint>

constexpr int B = 32, N = 2000, NPAD = 2048, D = 25088;
constexpr int ITOT = D / 64;      // 392 k-iters (dots)
constexpr int KC   = 18;          // dots k-chunks -> 16*18 = 288 blocks
constexpr int RIT  = NPAD / 64;   // 32 n-iters (read)
constexpr int LDA  = 72;          // smem row stride in bf16 (144B, ldmatrix conflict-free)

constexpr float EPS = 1e-8f, PI_2C = 3.14159f * 0.5f;

__device__ float         g_part[KC * B * NPAD];
__device__ float         g_msq [KC * NPAD];
__device__ __nv_bfloat16 g_whi [B * NPAD];   // padding [2000,2048) stays 0
__device__ __nv_bfloat16 g_wlo [B * NPAD];

__device__ __forceinline__ uint32_t smem_u32(const void* p) {
    uint32_t a;
    asm("{ .reg .u64 t; cvta.to.shared.u64 t, %1; cvt.u32.u64 %0, t; }" : "=r"(a) : "l"(p));
    return a;
}
__device__ __forceinline__ void ldm4(uint32_t& r0, uint32_t& r1, uint32_t& r2, uint32_t& r3, uint32_t a) {
    asm volatile("ldmatrix.sync.aligned.m8n8.x4.shared.b16 {%0,%1,%2,%3}, [%4];"
                 : "=r"(r0), "=r"(r1), "=r"(r2), "=r"(r3) : "r"(a));
}
__device__ __forceinline__ void mma16816(float* c, uint32_t a0, uint32_t a1, uint32_t a2, uint32_t a3,
                                         uint32_t b0, uint32_t b1) {
    asm volatile("mma.sync.aligned.m16n8k16.row.col.f32.bf16.bf16.f32 "
                 "{%0,%1,%2,%3}, {%4,%5,%6,%7}, {%8,%9}, {%0,%1,%2,%3};"
                 : "+f"(c[0]), "+f"(c[1]), "+f"(c[2]), "+f"(c[3])
                 : "r"(a0), "r"(a1), "r"(a2), "r"(a3), "r"(b0), "r"(b1));
}
__device__ __forceinline__ uint32_t bf2(float a, float b) {
    __nv_bfloat162 h = __floats2bfloat162_rn(a, b);
    return *(uint32_t*)&h;
}

// ---------------------------------------------------------------------------
// Kernel 1: dots^T partials. A = mem tile [128 n][64 d], B = key [32 b][64 d],
// single-pass bf16 (error analysis: final rel err ~3e-5). Grid (16, KC), 256 thr.
// Warp w: M-rows n_local = 16w..16w+15, full N=32 (4 n8 frags).
// ---------------------------------------------------------------------------
__global__ __launch_bounds__(256) void dots_kernel(
    const float* __restrict__ key, const float* __restrict__ mem)
{
    __shared__ __align__(16) __nv_bfloat16 As[2][128 * LDA];
    __shared__ __align__(16) __nv_bfloat16 Bs[2][32 * LDA];
    __shared__ float msqs[128];
    const int tid = threadIdx.x, w = tid >> 5, t = tid & 31;
    const int n0 = blockIdx.x * 128, kc = blockIdx.y;
    const int it0 = kc * ITOT / KC, it1 = (kc + 1) * ITOT / KC;
    if (tid < 128) msqs[tid] = 0.f;

    const int arow = tid >> 1, ac = tid & 1;
    const bool aok = (n0 + arow) < N;
    const float* aptr = mem + (long long)(aok ? (n0 + arow) : 0) * D;

    float4 rA[8], rB[2];
    float msqa = 0.f;
    {
        const int d0 = it0 * 64;
        #pragma unroll
        for (int p = 0; p < 8; p++)
            rA[p] = aok ? *(const float4*)&aptr[d0 + (ac * 8 + p) * 4] : make_float4(0,0,0,0);
        #pragma unroll
        for (int q = 0; q < 2; q++) {
            const int idx = tid + 256 * q;
            rB[q] = *(const float4*)&key[(idx >> 4) * D + d0 + (idx & 15) * 4];
        }
    }

    float acc[4][4];
    #pragma unroll
    for (int f = 0; f < 4; f++)
        #pragma unroll
        for (int i = 0; i < 4; i++) acc[f][i] = 0.f;

    for (int it = it0; it < it1; ++it) {
        const int buf = it & 1;
        __nv_bfloat16* A = As[buf];
        #pragma unroll
        for (int p = 0; p < 8; p++) {
            const float4 v = rA[p];
            msqa = fmaf(v.x, v.x, fmaf(v.y, v.y, fmaf(v.z, v.z, fmaf(v.w, v.w, msqa))));
            *(uint2*)&A[arow * LDA + (ac * 8 + p) * 4] = make_uint2(bf2(v.x, v.y), bf2(v.z, v.w));
        }
        #pragma unroll
        for (int q = 0; q < 2; q++) {
            const int idx = tid + 256 * q;
            const float4 v = rB[q];
            *(uint2*)&Bs[buf][(idx >> 4) * LDA + (idx & 15) * 4] = make_uint2(bf2(v.x, v.y), bf2(v.z, v.w));
        }
        __syncthreads();
        if (it + 1 < it1) {
            const int d0 = (it + 1) * 64;
            #pragma unroll
            for (int p = 0; p < 8; p++)
                rA[p] = aok ? *(const float4*)&aptr[d0 + (ac * 8 + p) * 4] : make_float4(0,0,0,0);
            #pragma unroll
            for (int q = 0; q < 2; q++) {
                const int idx = tid + 256 * q;
                rB[q] = *(const float4*)&key[(idx >> 4) * D + d0 + (idx & 15) * 4];
            }
        }
        const uint32_t ab = smem_u32(As[buf]), bb = smem_u32(Bs[buf]);
        const int ar = (t & 7) + ((t >> 3) & 1) * 8;    // A: row within 16, col half by t>>4
        const int ac8 = ((t >> 4) & 1) * 8;
        const int br = (t & 7) + ((t >> 4) & 1) * 8;    // B: row within 16, col half by t>>3
        const int bc8 = ((t >> 3) & 1) * 8;
        #pragma unroll
        for (int kk = 0; kk < 4; ++kk) {
            uint32_t a0, a1, a2, a3, b[8];
            ldm4(a0, a1, a2, a3, ab + 2u * ((w * 16 + ar) * LDA + kk * 16 + ac8));
            ldm4(b[0], b[1], b[2], b[3], bb + 2u * ((br) * LDA + kk * 16 + bc8));
            ldm4(b[4], b[5], b[6], b[7], bb + 2u * ((16 + br) * LDA + kk * 16 + bc8));
            #pragma unroll
            for (int f = 0; f < 4; f++)
                mma16816(acc[f], a0, a1, a2, a3, b[2 * f], b[2 * f + 1]);
        }
        __syncthreads();
    }

    // epilogue: C[n_local][b] -> g_part[kc][b][n]
    const int nrow = n0 + w * 16 + (t >> 2);
    const int bc = 2 * (t & 3);
    #pragma unroll
    for (int f = 0; f < 4; f++) {
        g_part[(kc * B + 8 * f + bc    ) * NPAD + nrow    ] = acc[f][0];
        g_part[(kc * B + 8 * f + bc + 1) * NPAD + nrow    ] = acc[f][1];
        g_part[(kc * B + 8 * f + bc    ) * NPAD + nrow + 8] = acc[f][2];
        g_part[(kc * B + 8 * f + bc + 1) * NPAD + nrow + 8] = acc[f][3];
    }
    atomicAdd(&msqs[arow], msqa);
    __syncthreads();
    if (tid < 128) g_msq[kc * NPAD + n0 + tid] = msqs[tid];
}

// ---------------------------------------------------------------------------
// Kernel 2: norms + reduce + tan + softmax -> w split hi/lo bf16
// ---------------------------------------------------------------------------
__global__ __launch_bounds__(256) void softmax_kernel(const float* __restrict__ key)
{
    const int b = blockIdx.x, tid = threadIdx.x;
    __shared__ float red[256];
    float s = 0.f;
    for (int i = tid; i < D; i += 256) { const float v = key[b * D + i]; s = fmaf(v, v, s); }
    red[tid] = s; __syncthreads();
    for (int o = 128; o > 0; o >>= 1) { if (tid < o) red[tid] += red[tid + o]; __syncthreads(); }
    const float knorm = fmaxf(sqrtf(red[0]), EPS);
    __syncthreads();

    float sv[8], lmax = -CUDART_INF_F;
    #pragma unroll
    for (int j = 0; j < 8; j++) {
        const int n = tid + 256 * j;
        if (n < N) {
            float dot = 0.f, ms = 0.f;
            for (int c = 0; c < KC; c++) {
                dot += g_part[(c * B + b) * NPAD + n];
                ms  += g_msq[c * NPAD + n];
            }
            const float mn = fmaxf(sqrtf(ms), EPS);
            sv[j] = tanf((dot / (knorm * mn)) * PI_2C);
            lmax = fmaxf(lmax, sv[j]);
        } else sv[j] = -CUDART_INF_F;
    }
    red[tid] = lmax; __syncthreads();
    for (int o = 128; o > 0; o >>= 1) { if (tid < o) red[tid] = fmaxf(red[tid], red[tid+o]); __syncthreads(); }
    const float mx = red[0];
    __syncthreads();

    float ev[8], ls = 0.f;
    #pragma unroll
    for (int j = 0; j < 8; j++) {
        const int n = tid + 256 * j;
        ev[j] = (n < N) ? expf(sv[j] - mx) : 0.f;
        ls += ev[j];
    }
    red[tid] = ls; __syncthreads();
    for (int o = 128; o > 0; o >>= 1) { if (tid < o) red[tid] += red[tid + o]; __syncthreads(); }
    const float inv = 1.f / red[0];
    #pragma unroll
    for (int j = 0; j < 8; j++) {
        const int n = tid + 256 * j;
        if (n < N) {
            const float wv = ev[j] * inv;
            const __nv_bfloat16 hi = __float2bfloat16(wv);
            g_whi[b * NPAD + n] = hi;
            g_wlo[b * NPAD + n] = __float2bfloat16(wv - __bfloat162float(hi));
        }
    }
}

// ---------------------------------------------------------------------------
// Kernel 3: out[b,d] = sum_n w[b,n] m[n,d]. Grid 392 d-blocks, 256 thr.
// A = w tile [64 rows: 0-31 hi, 32-63 lo][64 n]; B = m tile transposed [64 d][64 n],
// split hi/lo (two B passes). Warp (mi=w&3, nj=w>>2): M16 x N32.
// Epilogue: out_b = C[row b] + C[row b+32] via smem reduce. Dyn smem 63488.
// ---------------------------------------------------------------------------
__global__ __launch_bounds__(256) void read_kernel(
    const float* __restrict__ mem, float* __restrict__ out)
{
    extern __shared__ __align__(16) char sm[];
    __nv_bfloat16* Aw = (__nv_bfloat16*)sm;              // 2 x 64*LDA
    __nv_bfloat16* Bh = (__nv_bfloat16*)(sm + 18432);    // 2 x 64*LDA
    __nv_bfloat16* Bl = (__nv_bfloat16*)(sm + 36864);    // 2 x 64*LDA
    float* red = (float*)(sm + 55296);                   // 4 slots x 32 thr x 16
    const int tid = threadIdx.x, w = tid >> 5, t = tid & 31;
    const int d0 = blockIdx.x * 64;
    const int mi = w & 3, nj = w >> 2;

    const int warow = tid >> 3, wach = tid & 7;          // w-tile: row 0..31, 16B chunk

    uint4 rAh, rAl; float4 rB[4];
    {
        rAh = *(const uint4*)&g_whi[warow * NPAD + wach * 8];
        rAl = *(const uint4*)&g_wlo[warow * NPAD + wach * 8];
        #pragma unroll
        for (int p = 0; p < 4; p++) {
            const int idx = tid + 256 * p, n = idx >> 4;
            rB[p] = (n < N) ? *(const float4*)&mem[(long long)n * D + d0 + (idx & 15) * 4]
                            : make_float4(0,0,0,0);
        }
    }

    float acc[4][4];
    #pragma unroll
    for (int f = 0; f < 4; f++)
        #pragma unroll
        for (int i = 0; i < 4; i++) acc[f][i] = 0.f;

    for (int it = 0; it < RIT; ++it) {
        const int buf = it & 1;
        *(uint4*)&Aw[buf * 64 * LDA + warow * LDA + wach * 8] = rAh;
        *(uint4*)&Aw[buf * 64 * LDA + (32 + warow) * LDA + wach * 8] = rAl;
        #pragma unroll
        for (int p = 0; p < 4; p++) {
            const int idx = tid + 256 * p;
            const int n = idx & 1023 ? (idx >> 4) - (it * 0) : (idx >> 4); // (no-op; clarity)
            const int nn = idx >> 4, dch = idx & 15;
            const float vv[4] = {rB[p].x, rB[p].y, rB[p].z, rB[p].w};
            #pragma unroll
            for (int i = 0; i < 4; i++) {
                const __nv_bfloat16 h = __float2bfloat16(vv[i]);
                Bh[buf * 64 * LDA + (4 * dch + i) * LDA + nn] = h;
                Bl[buf * 64 * LDA + (4 * dch + i) * LDA + nn] =
                    __float2bfloat16(vv[i] - __bfloat162float(h));
            }
        }
        __syncthreads();
        if (it + 1 < RIT) {
            const int nb = (it + 1) * 64;
            rAh = *(const uint4*)&g_whi[warow * NPAD + nb + wach * 8];
            rAl = *(const uint4*)&g_wlo[warow * NPAD + nb + wach * 8];
            #pragma unroll
            for (int p = 0; p < 4; p++) {
                const int idx = tid + 256 * p, n = nb + (idx >> 4);
                rB[p] = (n < N) ? *(const float4*)&mem[(long long)n * D + d0 + (idx & 15) * 4]
                                : make_float4(0,0,0,0);
            }
        }
        const uint32_t ab = smem_u32(Aw + buf * 64 * LDA);
        const uint32_t bhb = smem_u32(Bh + buf * 64 * LDA);
        const uint32_t blb = smem_u32(Bl + buf * 64 * LDA);
        const int ar = (t & 7) + ((t >> 3) & 1) * 8, ac8 = ((t >> 4) & 1) * 8;
        const int br = (t & 7) + ((t >> 4) & 1) * 8, bc8 = ((t >> 3) & 1) * 8;
        #pragma unroll
        for (int kk = 0; kk < 4; ++kk) {
            uint32_t a0, a1, a2, a3, b[8];
            ldm4(a0, a1, a2, a3, ab + 2u * ((mi * 16 + ar) * LDA + kk * 16 + ac8));
            ldm4(b[0], b[1], b[2], b[3], bhb + 2u * ((nj * 32 + br) * LDA + kk * 16 + bc8));
            ldm4(b[4], b[5], b[6], b[7], bhb + 2u * ((nj * 32 + 16 + br) * LDA + kk * 16 + bc8));
            #pragma unroll
            for (int f = 0; f < 4; f++)
                mma16816(acc[f], a0, a1, a2, a3, b[2 * f], b[2 * f + 1]);
            ldm4(b[0], b[1], b[2], b[3], blb + 2u * ((nj * 32 + br) * LDA + kk * 16 + bc8));
            ldm4(b[4], b[5], b[6], b[7], blb + 2u * ((nj * 32 + 16 + br) * LDA + kk * 16 + bc8));
            #pragma unroll
            for (int f = 0; f < 4; f++)
                mma16816(acc[f], a0, a1, a2, a3, b[2 * f], b[2 * f + 1]);
        }
        __syncthreads();
    }

    // epilogue: rows 32-63 (mi 2,3 = w_lo part) added into rows 0-31 (w_hi part)
    if (mi >= 2) {
        const int slot = nj * 2 + (mi - 2);
        #pragma unroll
        for (int f = 0; f < 4; f++)
            #pragma unroll
            for (int i = 0; i < 4; i++)
                red[(slot * 32 + t) * 16 + f * 4 + i] = acc[f][i];
    }
    __syncthreads();
    if (mi < 2) {
        const int slot = nj * 2 + mi;
        #pragma unroll
        for (int f = 0; f < 4; f++)
            #pragma unroll
            for (int i = 0; i < 4; i++)
                acc[f][i] += red[(slot * 32 + t) * 16 + f * 4 + i];
        const int b = mi * 16 + (t >> 2);
        #pragma unroll
        for (int f = 0; f < 4; f++) {
            const int col = d0 + nj * 32 + 8 * f + 2 * (t & 3);
            *(float2*)&out[b * D + col]       = make_float2(acc[f][0], acc[f][1]);
            *(float2*)&out[(b + 8) * D + col] = make_float2(acc[f][2], acc[f][3]);
        }
    }
}

// ---------------------------------------------------------------------------
extern "C" void kernel_launch(void* const* d_in, const int* in_sizes, int n_in,
                              void* d_out, int out_size)
{
    const float* key = (const float*)d_in[0];
    const float* mem = (const float*)d_in[1];
    float* out = (float*)d_out;

    cudaFuncSetAttribute(read_kernel, cudaFuncAttributeMaxDynamicSharedMemorySize, 63488);

    dots_kernel<<<dim3(16, KC), 256>>>(key, mem);
    softmax_kernel<<<32, 256>>>(key);
    read_kernel<<<D / 64, 256, 63488>>>(mem, out);
}

// round 6
// speedup vs baseline: 3.0212x; 1.4893x over previous
#include <cuda_runtime.h>
#include <cuda_fp16.h>
#include <math_constants.h>
#include <cstdint>

constexpr int B = 32, N = 2000, NPAD = 2048, D = 25088;
constexpr int ITOT = D / 64;     // 392 k-iters (dots)
constexpr int KC   = 18;         // dots k-chunks -> 16*18 = 288 blocks
constexpr int RIT  = NPAD / 64;  // 32 n-iters (read)

constexpr float EPS = 1e-8f, PI_2C = 3.14159f * 0.5f;

__device__ float  g_part[KC * B * NPAD];
__device__ float  g_msq [KC * NPAD];
__device__ __half g_kh  [B * D];        // key pre-converted to fp16
__device__ __half g_whi [B * NPAD];     // padding [2000,2048) stays 0
__device__ __half g_wlo [B * NPAD];

__device__ __forceinline__ uint32_t smem_u32(const void* p) {
    uint32_t a;
    asm("{ .reg .u64 t; cvta.to.shared.u64 t, %1; cvt.u32.u64 %0, t; }" : "=r"(a) : "l"(p));
    return a;
}
__device__ __forceinline__ void ldm4(uint32_t& r0, uint32_t& r1, uint32_t& r2, uint32_t& r3, uint32_t a) {
    asm volatile("ldmatrix.sync.aligned.m8n8.x4.shared.b16 {%0,%1,%2,%3}, [%4];"
                 : "=r"(r0), "=r"(r1), "=r"(r2), "=r"(r3) : "r"(a));
}
__device__ __forceinline__ void ldm4t(uint32_t& r0, uint32_t& r1, uint32_t& r2, uint32_t& r3, uint32_t a) {
    asm volatile("ldmatrix.sync.aligned.m8n8.x4.trans.shared.b16 {%0,%1,%2,%3}, [%4];"
                 : "=r"(r0), "=r"(r1), "=r"(r2), "=r"(r3) : "r"(a));
}
__device__ __forceinline__ void mma_h(float* c, uint32_t a0, uint32_t a1, uint32_t a2, uint32_t a3,
                                      uint32_t b0, uint32_t b1) {
    asm volatile("mma.sync.aligned.m16n8k16.row.col.f32.f16.f16.f32 "
                 "{%0,%1,%2,%3}, {%4,%5,%6,%7}, {%8,%9}, {%0,%1,%2,%3};"
                 : "+f"(c[0]), "+f"(c[1]), "+f"(c[2]), "+f"(c[3])
                 : "r"(a0), "r"(a1), "r"(a2), "r"(a3), "r"(b0), "r"(b1));
}
__device__ __forceinline__ uint32_t h2(float a, float b) {
    __half2 h = __floats2half2_rn(a, b);
    return *(uint32_t*)&h;
}

// ---------------------------------------------------------------------------
// Kernel 0: key fp32 -> fp16. Grid 784 x 256.
// ---------------------------------------------------------------------------
__global__ __launch_bounds__(256) void keyconv_kernel(const float* __restrict__ key)
{
    const int i = blockIdx.x * 256 + threadIdx.x;
    const float4 v = ((const float4*)key)[i];
    ((uint2*)g_kh)[i] = make_uint2(h2(v.x, v.y), h2(v.z, v.w));
}

// ---------------------------------------------------------------------------
// Kernel 1: dots^T[n,b] partials + m-norm partials. NO smem, no syncs.
// Grid (16 n-tiles, 18 k-chunks), 256 thr. Warp w owns M-rows 16w..16w+15.
// A (mem fp32) loaded as fragment float2 pairs, converted in-register.
// B (g_kh fp16) loaded as fragment u32 pairs (L1-resident across warps).
// ---------------------------------------------------------------------------
__global__ __launch_bounds__(256) void dots_kernel(const float* __restrict__ mem)
{
    const int tid = threadIdx.x, w = tid >> 5, t = tid & 31;
    const int n0 = blockIdx.x * 128, kc = blockIdx.y;
    const int it0 = kc * ITOT / KC, it1 = (kc + 1) * ITOT / KC;
    const int r0 = n0 + w * 16 + (t >> 2);   // A row (n) for a0/a2
    const int qc = 2 * (t & 3);              // k-col base within 16
    const bool ok0 = r0 < N, ok1 = (r0 + 8) < N;
    const float* p0 = mem + (long long)(ok0 ? r0 : 0) * D;
    const float* p1 = mem + (long long)(ok1 ? r0 + 8 : 0) * D;
    const __half* kb = g_kh + (t >> 2) * D;  // B row (b) = t/4 (+8 per nf)

    float acc[4][4];
    #pragma unroll
    for (int f = 0; f < 4; f++)
        #pragma unroll
        for (int i = 0; i < 4; i++) acc[f][i] = 0.f;
    float ms0 = 0.f, ms1 = 0.f;

    for (int it = it0; it < it1; ++it) {
        const int d0 = it * 64;
        float2 fa[4][4];                      // [kk][frag a0..a3]
        #pragma unroll
        for (int kk = 0; kk < 4; kk++) {
            const int c = d0 + kk * 16 + qc;
            fa[kk][0] = ok0 ? *(const float2*)&p0[c]     : make_float2(0.f, 0.f);
            fa[kk][1] = ok1 ? *(const float2*)&p1[c]     : make_float2(0.f, 0.f);
            fa[kk][2] = ok0 ? *(const float2*)&p0[c + 8] : make_float2(0.f, 0.f);
            fa[kk][3] = ok1 ? *(const float2*)&p1[c + 8] : make_float2(0.f, 0.f);
        }
        #pragma unroll
        for (int kk = 0; kk < 4; kk++) {
            ms0 = fmaf(fa[kk][0].x, fa[kk][0].x, fmaf(fa[kk][0].y, fa[kk][0].y, ms0));
            ms0 = fmaf(fa[kk][2].x, fa[kk][2].x, fmaf(fa[kk][2].y, fa[kk][2].y, ms0));
            ms1 = fmaf(fa[kk][1].x, fa[kk][1].x, fmaf(fa[kk][1].y, fa[kk][1].y, ms1));
            ms1 = fmaf(fa[kk][3].x, fa[kk][3].x, fmaf(fa[kk][3].y, fa[kk][3].y, ms1));
            const uint32_t a0 = h2(fa[kk][0].x, fa[kk][0].y);
            const uint32_t a1 = h2(fa[kk][1].x, fa[kk][1].y);
            const uint32_t a2 = h2(fa[kk][2].x, fa[kk][2].y);
            const uint32_t a3 = h2(fa[kk][3].x, fa[kk][3].y);
            #pragma unroll
            for (int nf = 0; nf < 4; nf++) {
                const __half* bp = kb + nf * 8 * D + d0 + kk * 16 + qc;
                const uint32_t b0 = *(const uint32_t*)bp;
                const uint32_t b1 = *(const uint32_t*)(bp + 8);
                mma_h(acc[nf], a0, a1, a2, a3, b0, b1);
            }
        }
    }

    // C[n_local][b] -> g_part[kc][b][n]  (rows >= N write garbage inside NPAD; softmax guards)
    const int nrow = n0 + w * 16 + (t >> 2);
    #pragma unroll
    for (int nf = 0; nf < 4; nf++) {
        g_part[(kc * B + 8 * nf + qc    ) * NPAD + nrow    ] = acc[nf][0];
        g_part[(kc * B + 8 * nf + qc + 1) * NPAD + nrow    ] = acc[nf][1];
        g_part[(kc * B + 8 * nf + qc    ) * NPAD + nrow + 8] = acc[nf][2];
        g_part[(kc * B + 8 * nf + qc + 1) * NPAD + nrow + 8] = acc[nf][3];
    }
    // m-norm partials: quad-reduce (lanes sharing t>>2), warp exclusively owns its rows
    ms0 += __shfl_xor_sync(0xffffffffu, ms0, 1);
    ms0 += __shfl_xor_sync(0xffffffffu, ms0, 2);
    ms1 += __shfl_xor_sync(0xffffffffu, ms1, 1);
    ms1 += __shfl_xor_sync(0xffffffffu, ms1, 2);
    if ((t & 3) == 0) {
        g_msq[kc * NPAD + n0 + w * 16 + (t >> 2)    ] = ms0;
        g_msq[kc * NPAD + n0 + w * 16 + (t >> 2) + 8] = ms1;
    }
}

// ---------------------------------------------------------------------------
// Kernel 2: norms + reduce partials + tan + softmax -> w split hi/lo fp16
// ---------------------------------------------------------------------------
__global__ __launch_bounds__(256) void softmax_kernel(const float* __restrict__ key)
{
    const int b = blockIdx.x, tid = threadIdx.x;
    __shared__ float red[256];
    float s = 0.f;
    for (int i = tid; i < D; i += 256) { const float v = key[b * D + i]; s = fmaf(v, v, s); }
    red[tid] = s; __syncthreads();
    for (int o = 128; o > 0; o >>= 1) { if (tid < o) red[tid] += red[tid + o]; __syncthreads(); }
    const float knorm = fmaxf(sqrtf(red[0]), EPS);
    __syncthreads();

    float sv[8], lmax = -CUDART_INF_F;
    #pragma unroll
    for (int j = 0; j < 8; j++) {
        const int n = tid + 256 * j;
        if (n < N) {
            float dot = 0.f, ms = 0.f;
            for (int c = 0; c < KC; c++) {
                dot += g_part[(c * B + b) * NPAD + n];
                ms  += g_msq[c * NPAD + n];
            }
            const float mn = fmaxf(sqrtf(ms), EPS);
            sv[j] = tanf((dot / (knorm * mn)) * PI_2C);
            lmax = fmaxf(lmax, sv[j]);
        } else sv[j] = -CUDART_INF_F;
    }
    red[tid] = lmax; __syncthreads();
    for (int o = 128; o > 0; o >>= 1) { if (tid < o) red[tid] = fmaxf(red[tid], red[tid+o]); __syncthreads(); }
    const float mx = red[0];
    __syncthreads();

    float ev[8], ls = 0.f;
    #pragma unroll
    for (int j = 0; j < 8; j++) {
        const int n = tid + 256 * j;
        ev[j] = (n < N) ? expf(sv[j] - mx) : 0.f;
        ls += ev[j];
    }
    red[tid] = ls; __syncthreads();
    for (int o = 128; o > 0; o >>= 1) { if (tid < o) red[tid] += red[tid + o]; __syncthreads(); }
    const float inv = 1.f / red[0];
    #pragma unroll
    for (int j = 0; j < 8; j++) {
        const int n = tid + 256 * j;
        if (n < N) {
            const float wv = ev[j] * inv;
            const __half hi = __float2half(wv);
            g_whi[b * NPAD + n] = hi;
            g_wlo[b * NPAD + n] = __float2half(wv - __half2float(hi));
        }
    }
}

// ---------------------------------------------------------------------------
// Kernel 3: out[b,d] = sum_n w[b,n] m[n,d]. Grid 196 (d-tile 128), 256 thr.
// A = w [64 rows: 0-31 hi, 32-63 lo][64 n] fp16; B = m tile natural [64 n][128 d]
// fp16 single-pass (err ~2.8e-4), fragments via ldmatrix.trans.
// Warps: mi = w>>2 (hi/lo product), nj = w&3 (32-d slice). Epilogue adds mi=1 into mi=0.
// smem: Aw 2x64x72 h (18432B) | Bt 2x64x136 h (34816B). Dyn total 53248.
// ---------------------------------------------------------------------------
__global__ __launch_bounds__(256) void read_kernel(
    const float* __restrict__ mem, float* __restrict__ out)
{
    extern __shared__ __align__(16) char sm[];
    __half* Aw = (__half*)sm;                  // [buf][64][72]
    __half* Bt = (__half*)(sm + 18432);        // [buf][64][136]
    float*  red = (float*)(sm + 18432);        // epilogue reuse (16KB)
    const uint32_t sbA = smem_u32(Aw), sbB = smem_u32(Bt);
    const int tid = threadIdx.x, w = tid >> 5, t = tid & 31;
    const int d0 = blockIdx.x * 128;
    const int mi = w >> 2, nj = w & 3;

    const int wr = tid >> 3, ch = tid & 7;     // w loads: row 0..31, 8-half chunk

    uint4 rAh, rAl; float4 rB[8];
    {
        rAh = *(const uint4*)&g_whi[wr * NPAD + ch * 8];
        rAl = *(const uint4*)&g_wlo[wr * NPAD + ch * 8];
        #pragma unroll
        for (int p = 0; p < 8; p++) {
            const int idx = tid + 256 * p, row = idx >> 5, c4 = idx & 31;
            rB[p] = (row < N) ? *(const float4*)&mem[(long long)row * D + d0 + c4 * 4]
                              : make_float4(0.f, 0.f, 0.f, 0.f);
        }
    }

    float acc[2][4][4];
    #pragma unroll
    for (int af = 0; af < 2; af++)
        #pragma unroll
        for (int bf = 0; bf < 4; bf++)
            #pragma unroll
            for (int i = 0; i < 4; i++) acc[af][bf][i] = 0.f;

    for (int it = 0; it < RIT; ++it) {
        const int buf = it & 1;
        __half* A = Aw + buf * 64 * 72;
        __half* Bm = Bt + buf * 64 * 136;
        *(uint4*)&A[wr * 72 + ch * 8]        = rAh;
        *(uint4*)&A[(32 + wr) * 72 + ch * 8] = rAl;
        #pragma unroll
        for (int p = 0; p < 8; p++) {
            const int idx = tid + 256 * p, row = idx >> 5, c4 = idx & 31;
            *(uint2*)&Bm[row * 136 + c4 * 4] = make_uint2(h2(rB[p].x, rB[p].y), h2(rB[p].z, rB[p].w));
        }
        __syncthreads();
        if (it + 1 < RIT) {
            const int nb = (it + 1) * 64;
            rAh = *(const uint4*)&g_whi[wr * NPAD + nb + ch * 8];
            rAl = *(const uint4*)&g_wlo[wr * NPAD + nb + ch * 8];
            #pragma unroll
            for (int p = 0; p < 8; p++) {
                const int idx = tid + 256 * p, row = idx >> 5, c4 = idx & 31;
                const int n = nb + row;
                rB[p] = (n < N) ? *(const float4*)&mem[(long long)n * D + d0 + c4 * 4]
                                : make_float4(0.f, 0.f, 0.f, 0.f);
            }
        }
        // compute
        const int lr = (t & 7) + 8 * ((t >> 3) & 1);   // lane row within 16
        const int lh = 8 * (t >> 4);                   // lane col half
        #pragma unroll
        for (int kk = 0; kk < 4; kk++) {
            uint32_t a[2][4], bq[2][4];
            #pragma unroll
            for (int af = 0; af < 2; af++) {
                const uint32_t addr = sbA + 2u * (buf * 64 * 72 + (mi * 32 + af * 16 + lr) * 72 + kk * 16 + lh);
                ldm4(a[af][0], a[af][1], a[af][2], a[af][3], addr);
            }
            #pragma unroll
            for (int bh = 0; bh < 2; bh++) {
                const uint32_t addr = sbB + 2u * (buf * 64 * 136 + (kk * 16 + lr) * 136 + nj * 32 + bh * 16 + lh);
                ldm4t(bq[bh][0], bq[bh][1], bq[bh][2], bq[bh][3], addr);
            }
            #pragma unroll
            for (int af = 0; af < 2; af++)
                #pragma unroll
                for (int bh = 0; bh < 2; bh++) {
                    mma_h(acc[af][2 * bh],     a[af][0], a[af][1], a[af][2], a[af][3], bq[bh][0], bq[bh][1]);
                    mma_h(acc[af][2 * bh + 1], a[af][0], a[af][1], a[af][2], a[af][3], bq[bh][2], bq[bh][3]);
                }
        }
        __syncthreads();
    }

    // epilogue: mi=1 (w_lo product) added into mi=0 (w_hi product)
    if (mi == 1) {
        #pragma unroll
        for (int af = 0; af < 2; af++)
            #pragma unroll
            for (int bf = 0; bf < 4; bf++)
                #pragma unroll
                for (int i = 0; i < 4; i++)
                    red[(nj * 32 + t) * 32 + af * 16 + bf * 4 + i] = acc[af][bf][i];
    }
    __syncthreads();
    if (mi == 0) {
        #pragma unroll
        for (int af = 0; af < 2; af++)
            #pragma unroll
            for (int bf = 0; bf < 4; bf++) {
                float c0 = acc[af][bf][0] + red[(nj * 32 + t) * 32 + af * 16 + bf * 4 + 0];
                float c1 = acc[af][bf][1] + red[(nj * 32 + t) * 32 + af * 16 + bf * 4 + 1];
                float c2 = acc[af][bf][2] + red[(nj * 32 + t) * 32 + af * 16 + bf * 4 + 2];
                float c3 = acc[af][bf][3] + red[(nj * 32 + t) * 32 + af * 16 + bf * 4 + 3];
                const int b  = af * 16 + (t >> 2);
                const int col = d0 + nj * 32 + bf * 8 + 2 * (t & 3);
                *(float2*)&out[b * D + col]       = make_float2(c0, c1);
                *(float2*)&out[(b + 8) * D + col] = make_float2(c2, c3);
            }
    }
}

// ---------------------------------------------------------------------------
extern "C" void kernel_launch(void* const* d_in, const int* in_sizes, int n_in,
                              void* d_out, int out_size)
{
    const float* key = (const float*)d_in[0];
    const float* mem = (const float*)d_in[1];
    float* out = (float*)d_out;

    cudaFuncSetAttribute(read_kernel, cudaFuncAttributeMaxDynamicSharedMemorySize, 53248);

    keyconv_kernel<<<B * D / 4 / 256, 256>>>(key);
    dots_kernel<<<dim3(16, KC), 256>>>(mem);
    softmax_kernel<<<32, 256>>>(key);
    read_kernel<<<D / 128, 256, 53248>>>(mem, out);
}

// round 7
// speedup vs baseline: 4.3395x; 1.4364x over previous
#include <cuda_runtime.h>
#include <cuda_fp16.h>
#include <math_constants.h>
#include <cstdint>

constexpr int B = 32, N = 2000, NPAD = 2048, D = 25088;
constexpr int ITOT = D / 64;     // 392 k-iters (dots)
constexpr int KC   = 18;         // dots k-chunks
constexpr int RIT  = NPAD / 64;  // 32 n-iters (read)

constexpr float EPS = 1e-8f, PI_2C = 3.14159f * 0.5f;

__device__ float  g_part[KC * B * NPAD];
__device__ float  g_msq [KC * NPAD];
__device__ uint4  g_kb  [ITOT * 4 * 32 * 2];  // key prepacked in mma-fragment order
__device__ __half g_whi [B * NPAD];           // padding [2000,2048) stays 0
__device__ __half g_wlo [B * NPAD];

__device__ __forceinline__ uint32_t smem_u32(const void* p) {
    uint32_t a;
    asm("{ .reg .u64 t; cvta.to.shared.u64 t, %1; cvt.u32.u64 %0, t; }" : "=r"(a) : "l"(p));
    return a;
}
__device__ __forceinline__ void ldm4(uint32_t& r0, uint32_t& r1, uint32_t& r2, uint32_t& r3, uint32_t a) {
    asm volatile("ldmatrix.sync.aligned.m8n8.x4.shared.b16 {%0,%1,%2,%3}, [%4];"
                 : "=r"(r0), "=r"(r1), "=r"(r2), "=r"(r3) : "r"(a));
}
__device__ __forceinline__ void ldm4t(uint32_t& r0, uint32_t& r1, uint32_t& r2, uint32_t& r3, uint32_t a) {
    asm volatile("ldmatrix.sync.aligned.m8n8.x4.trans.shared.b16 {%0,%1,%2,%3}, [%4];"
                 : "=r"(r0), "=r"(r1), "=r"(r2), "=r"(r3) : "r"(a));
}
__device__ __forceinline__ void mma_h(float* c, uint32_t a0, uint32_t a1, uint32_t a2, uint32_t a3,
                                      uint32_t b0, uint32_t b1) {
    asm volatile("mma.sync.aligned.m16n8k16.row.col.f32.f16.f16.f32 "
                 "{%0,%1,%2,%3}, {%4,%5,%6,%7}, {%8,%9}, {%0,%1,%2,%3};"
                 : "+f"(c[0]), "+f"(c[1]), "+f"(c[2]), "+f"(c[3])
                 : "r"(a0), "r"(a1), "r"(a2), "r"(a3), "r"(b0), "r"(b1));
}
__device__ __forceinline__ uint32_t h2(float a, float b) {
    __half2 h = __floats2half2_rn(a, b);
    return *(uint32_t*)&h;
}

// ---------------------------------------------------------------------------
// Kernel 0: prepack key into per-(kstep,lane) B fragments. Grid 196 x 256.
// Step s = it*4+kk; lane t; fragment cols d = 64*(s>>2)+16*(s&3)+2*(t&3) (+8 for b1);
// rows b = (t>>2)+8*nf. Stored as 2 uint4: {b0[nf=0..3]}, {b1[nf=0..3]}.
// ---------------------------------------------------------------------------
__global__ __launch_bounds__(256) void prepack_kernel(const float* __restrict__ key)
{
    const int gid = blockIdx.x * 256 + threadIdx.x;   // 0..50175
    const int t = gid & 31, s = gid >> 5;
    const int d = (s >> 2) * 64 + (s & 3) * 16 + 2 * (t & 3);
    uint32_t v0[4], v1[4];
    #pragma unroll
    for (int nf = 0; nf < 4; nf++) {
        const int row = (t >> 2) + 8 * nf;
        const float2 x0 = *(const float2*)&key[row * D + d];
        const float2 x1 = *(const float2*)&key[row * D + d + 8];
        v0[nf] = h2(x0.x, x0.y);
        v1[nf] = h2(x1.x, x1.y);
    }
    g_kb[(s * 32 + t) * 2    ] = make_uint4(v0[0], v0[1], v0[2], v0[3]);
    g_kb[(s * 32 + t) * 2 + 1] = make_uint4(v1[0], v1[1], v1[2], v1[3]);
}

// ---------------------------------------------------------------------------
// Kernel 1: dots^T[n,b] partials + m-norm partials. No smem, register-pipelined.
// Grid (16 n-tiles, KC k-chunks), 256 thr. Warp w owns M-rows 16w..16w+15.
// Per k-step (16 cols): A = 4 LDG.64 fp32 (converted in-reg), B = 2 LDG.128
// from g_kb (warp-identical -> L1 broadcast). 2-stage register double buffer.
// ---------------------------------------------------------------------------
__global__ __launch_bounds__(256) void dots_kernel(const float* __restrict__ mem)
{
    const int tid = threadIdx.x, w = tid >> 5, t = tid & 31;
    const int n0 = blockIdx.x * 128, kc = blockIdx.y;
    const int it0 = kc * ITOT / KC, it1 = (kc + 1) * ITOT / KC;
    const int nst = (it1 - it0) * 4;
    const int r0 = n0 + w * 16 + (t >> 2);
    const int qc = 2 * (t & 3);
    const bool ok0 = r0 < N, ok1 = (r0 + 8) < N;
    const float* q0 = mem + (long long)(ok0 ? r0 : 0) * D + it0 * 64 + qc;
    const float* q1 = mem + (long long)(ok1 ? r0 + 8 : 0) * D + it0 * 64 + qc;
    const uint4* kb = g_kb + ((long long)(it0 * 4) * 32 + t) * 2;

    float acc[4][4];
    #pragma unroll
    for (int f = 0; f < 4; f++)
        #pragma unroll
        for (int i = 0; i < 4; i++) acc[f][i] = 0.f;
    float ms0 = 0.f, ms1 = 0.f;

    float2 fa[2][4]; uint4 fb[2][2];
    // preload step 0
    fa[0][0] = *(const float2*)q0;
    fa[0][1] = *(const float2*)q1;
    fa[0][2] = *(const float2*)(q0 + 8);
    fa[0][3] = *(const float2*)(q1 + 8);
    fb[0][0] = kb[0];
    fb[0][1] = kb[1];

    for (int j = 0; j < nst; ++j) {
        const int b = j & 1;
        if (j + 1 < nst) {
            const float* a0 = q0 + (j + 1) * 16;
            const float* a1 = q1 + (j + 1) * 16;
            fa[b ^ 1][0] = *(const float2*)a0;
            fa[b ^ 1][1] = *(const float2*)a1;
            fa[b ^ 1][2] = *(const float2*)(a0 + 8);
            fa[b ^ 1][3] = *(const float2*)(a1 + 8);
            fb[b ^ 1][0] = kb[(j + 1) * 64];
            fb[b ^ 1][1] = kb[(j + 1) * 64 + 1];
        }
        float2 f0 = fa[b][0], f1 = fa[b][1], f2v = fa[b][2], f3 = fa[b][3];
        if (!ok0) { f0 = make_float2(0.f, 0.f); f2v = make_float2(0.f, 0.f); }
        if (!ok1) { f1 = make_float2(0.f, 0.f); f3 = make_float2(0.f, 0.f); }
        ms0 = fmaf(f0.x, f0.x, fmaf(f0.y, f0.y, ms0));
        ms0 = fmaf(f2v.x, f2v.x, fmaf(f2v.y, f2v.y, ms0));
        ms1 = fmaf(f1.x, f1.x, fmaf(f1.y, f1.y, ms1));
        ms1 = fmaf(f3.x, f3.x, fmaf(f3.y, f3.y, ms1));
        const uint32_t a0 = h2(f0.x, f0.y), a1 = h2(f1.x, f1.y);
        const uint32_t a2 = h2(f2v.x, f2v.y), a3 = h2(f3.x, f3.y);
        const uint4 B0 = fb[b][0], B1 = fb[b][1];
        mma_h(acc[0], a0, a1, a2, a3, B0.x, B1.x);
        mma_h(acc[1], a0, a1, a2, a3, B0.y, B1.y);
        mma_h(acc[2], a0, a1, a2, a3, B0.z, B1.z);
        mma_h(acc[3], a0, a1, a2, a3, B0.w, B1.w);
    }

    // C[n_local][b] -> g_part[kc][b][n]  (rows >= N write garbage in NPAD; softmax guards)
    const int nrow = n0 + w * 16 + (t >> 2);
    #pragma unroll
    for (int nf = 0; nf < 4; nf++) {
        g_part[(kc * B + 8 * nf + qc    ) * NPAD + nrow    ] = acc[nf][0];
        g_part[(kc * B + 8 * nf + qc + 1) * NPAD + nrow    ] = acc[nf][1];
        g_part[(kc * B + 8 * nf + qc    ) * NPAD + nrow + 8] = acc[nf][2];
        g_part[(kc * B + 8 * nf + qc + 1) * NPAD + nrow + 8] = acc[nf][3];
    }
    ms0 += __shfl_xor_sync(0xffffffffu, ms0, 1);
    ms0 += __shfl_xor_sync(0xffffffffu, ms0, 2);
    ms1 += __shfl_xor_sync(0xffffffffu, ms1, 1);
    ms1 += __shfl_xor_sync(0xffffffffu, ms1, 2);
    if ((t & 3) == 0) {
        g_msq[kc * NPAD + n0 + w * 16 + (t >> 2)    ] = ms0;
        g_msq[kc * NPAD + n0 + w * 16 + (t >> 2) + 8] = ms1;
    }
}

// ---------------------------------------------------------------------------
// Kernel 2: norms + reduce partials + tan + softmax -> w split hi/lo fp16
// ---------------------------------------------------------------------------
__global__ __launch_bounds__(256) void softmax_kernel(const float* __restrict__ key)
{
    const int b = blockIdx.x, tid = threadIdx.x;
    __shared__ float red[256];
    float s = 0.f;
    for (int i = tid; i < D; i += 256) { const float v = key[b * D + i]; s = fmaf(v, v, s); }
    red[tid] = s; __syncthreads();
    for (int o = 128; o > 0; o >>= 1) { if (tid < o) red[tid] += red[tid + o]; __syncthreads(); }
    const float knorm = fmaxf(sqrtf(red[0]), EPS);
    __syncthreads();

    float sv[8], lmax = -CUDART_INF_F;
    #pragma unroll
    for (int j = 0; j < 8; j++) {
        const int n = tid + 256 * j;
        if (n < N) {
            float dot = 0.f, ms = 0.f;
            for (int c = 0; c < KC; c++) {
                dot += g_part[(c * B + b) * NPAD + n];
                ms  += g_msq[c * NPAD + n];
            }
            const float mn = fmaxf(sqrtf(ms), EPS);
            sv[j] = tanf((dot / (knorm * mn)) * PI_2C);
            lmax = fmaxf(lmax, sv[j]);
        } else sv[j] = -CUDART_INF_F;
    }
    red[tid] = lmax; __syncthreads();
    for (int o = 128; o > 0; o >>= 1) { if (tid < o) red[tid] = fmaxf(red[tid], red[tid+o]); __syncthreads(); }
    const float mx = red[0];
    __syncthreads();

    float ev[8], ls = 0.f;
    #pragma unroll
    for (int j = 0; j < 8; j++) {
        const int n = tid + 256 * j;
        ev[j] = (n < N) ? expf(sv[j] - mx) : 0.f;
        ls += ev[j];
    }
    red[tid] = ls; __syncthreads();
    for (int o = 128; o > 0; o >>= 1) { if (tid < o) red[tid] += red[tid + o]; __syncthreads(); }
    const float inv = 1.f / red[0];
    #pragma unroll
    for (int j = 0; j < 8; j++) {
        const int n = tid + 256 * j;
        if (n < N) {
            const float wv = ev[j] * inv;
            const __half hi = __float2half(wv);
            g_whi[b * NPAD + n] = hi;
            g_wlo[b * NPAD + n] = __float2half(wv - __half2float(hi));
        }
    }
}

// ---------------------------------------------------------------------------
// Kernel 3: out[b,d] = sum_n w[b,n] m[n,d]. Grid 392 (d-tile 64), 256 thr.
// A = w [64 rows: 0-31 hi, 32-63 lo][64 n] fp16; B = m tile [64 n][64 d] fp16.
// Warps: mi = w>>2 (hi/lo), nj = w&3 (16-d slice). Epilogue adds mi=1 into mi=0.
// smem: Aw 2x64x72 (18432B) + Bt 2x64x72 (18432B) = 36864 dyn.
// ---------------------------------------------------------------------------
__global__ __launch_bounds__(256) void read_kernel(
    const float* __restrict__ mem, float* __restrict__ out)
{
    extern __shared__ __align__(16) char sm[];
    __half* Aw = (__half*)sm;                  // [buf][64][72]
    __half* Bt = (__half*)(sm + 18432);        // [buf][64][72]
    float*  red = (float*)sm;                  // epilogue reuse (8KB)
    const uint32_t sbA = smem_u32(Aw), sbB = smem_u32(Bt);
    const int tid = threadIdx.x, w = tid >> 5, t = tid & 31;
    const int d0 = blockIdx.x * 64;
    const int mi = w >> 2, nj = w & 3;
    const int wr = tid >> 3, ch = tid & 7;

    uint4 rAh, rAl; float4 rB[4];
    {
        rAh = *(const uint4*)&g_whi[wr * NPAD + ch * 8];
        rAl = *(const uint4*)&g_wlo[wr * NPAD + ch * 8];
        #pragma unroll
        for (int p = 0; p < 4; p++) {
            const int idx = tid + 256 * p, row = idx >> 4, c4 = idx & 15;
            rB[p] = (row < N) ? *(const float4*)&mem[(long long)row * D + d0 + c4 * 4]
                              : make_float4(0.f, 0.f, 0.f, 0.f);
        }
    }

    float acc[2][2][4];
    #pragma unroll
    for (int af = 0; af < 2; af++)
        #pragma unroll
        for (int bf = 0; bf < 2; bf++)
            #pragma unroll
            for (int i = 0; i < 4; i++) acc[af][bf][i] = 0.f;

    for (int it = 0; it < RIT; ++it) {
        const int buf = it & 1;
        __half* A  = Aw + buf * 64 * 72;
        __half* Bm = Bt + buf * 64 * 72;
        *(uint4*)&A[wr * 72 + ch * 8]        = rAh;
        *(uint4*)&A[(32 + wr) * 72 + ch * 8] = rAl;
        #pragma unroll
        for (int p = 0; p < 4; p++) {
            const int idx = tid + 256 * p, row = idx >> 4, c4 = idx & 15;
            *(uint2*)&Bm[row * 72 + c4 * 4] = make_uint2(h2(rB[p].x, rB[p].y), h2(rB[p].z, rB[p].w));
        }
        __syncthreads();
        if (it + 1 < RIT) {
            const int nb = (it + 1) * 64;
            rAh = *(const uint4*)&g_whi[wr * NPAD + nb + ch * 8];
            rAl = *(const uint4*)&g_wlo[wr * NPAD + nb + ch * 8];
            #pragma unroll
            for (int p = 0; p < 4; p++) {
                const int idx = tid + 256 * p, row = idx >> 4, c4 = idx & 15;
                const int n = nb + row;
                rB[p] = (n < N) ? *(const float4*)&mem[(long long)n * D + d0 + c4 * 4]
                                : make_float4(0.f, 0.f, 0.f, 0.f);
            }
        }
        const int lr = (t & 7) + 8 * ((t >> 3) & 1);
        const int lh = 8 * (t >> 4);
        #pragma unroll
        for (int kk = 0; kk < 4; kk++) {
            uint32_t a[2][4], bq[4];
            #pragma unroll
            for (int af = 0; af < 2; af++) {
                const uint32_t addr = sbA + 2u * (buf * 64 * 72 + (mi * 32 + af * 16 + lr) * 72 + kk * 16 + lh);
                ldm4(a[af][0], a[af][1], a[af][2], a[af][3], addr);
            }
            {
                const uint32_t addr = sbB + 2u * (buf * 64 * 72 + (kk * 16 + lr) * 72 + nj * 16 + lh);
                ldm4t(bq[0], bq[1], bq[2], bq[3], addr);
            }
            #pragma unroll
            for (int af = 0; af < 2; af++) {
                mma_h(acc[af][0], a[af][0], a[af][1], a[af][2], a[af][3], bq[0], bq[1]);
                mma_h(acc[af][1], a[af][0], a[af][1], a[af][2], a[af][3], bq[2], bq[3]);
            }
        }
        __syncthreads();
    }

    // epilogue: mi=1 (w_lo product) added into mi=0 (w_hi product)
    if (mi == 1) {
        #pragma unroll
        for (int af = 0; af < 2; af++)
            #pragma unroll
            for (int bf = 0; bf < 2; bf++)
                #pragma unroll
                for (int i = 0; i < 4; i++)
                    red[(nj * 32 + t) * 16 + af * 8 + bf * 4 + i] = acc[af][bf][i];
    }
    __syncthreads();
    if (mi == 0) {
        #pragma unroll
        for (int af = 0; af < 2; af++)
            #pragma unroll
            for (int bf = 0; bf < 2; bf++) {
                const float c0 = acc[af][bf][0] + red[(nj * 32 + t) * 16 + af * 8 + bf * 4 + 0];
                const float c1 = acc[af][bf][1] + red[(nj * 32 + t) * 16 + af * 8 + bf * 4 + 1];
                const float c2 = acc[af][bf][2] + red[(nj * 32 + t) * 16 + af * 8 + bf * 4 + 2];
                const float c3 = acc[af][bf][3] + red[(nj * 32 + t) * 16 + af * 8 + bf * 4 + 3];
                const int b   = af * 16 + (t >> 2);
                const int col = d0 + nj * 16 + bf * 8 + 2 * (t & 3);
                *(float2*)&out[b * D + col]       = make_float2(c0, c1);
                *(float2*)&out[(b + 8) * D + col] = make_float2(c2, c3);
            }
    }
}

// ---------------------------------------------------------------------------
extern "C" void kernel_launch(void* const* d_in, const int* in_sizes, int n_in,
                              void* d_out, int out_size)
{
    const float* key = (const float*)d_in[0];
    const float* mem = (const float*)d_in[1];
    float* out = (float*)d_out;

    cudaFuncSetAttribute(read_kernel, cudaFuncAttributeMaxDynamicSharedMemorySize, 36864);

    prepack_kernel<<<ITOT * 4 * 32 / 256, 256>>>(key);
    dots_kernel<<<dim3(16, KC), 256>>>(mem);
    softmax_kernel<<<32, 256>>>(key);
    read_kernel<<<D / 64, 256, 36864>>>(mem, out);
}